// round 15
// baseline (speedup 1.0000x reference)
#include <cuda_runtime.h>
#include <cuda_bf16.h>
#include <cstdint>

#define BATCH 4
#define NPTS  16384
#define ROWS  (BATCH*NPTS)     // 65536
#define CIMG  64
#define KIMG  1024
#define D1    128
#define D2    64
#define BN_EPS 1e-5f
#define NB    296              // persistent blocks (2 per SM on 148 SMs)

// ---------------- global scratch (no allocations allowed) ----------------
__device__ __align__(16) float g_y1[(size_t)ROWS*D1];
__device__ __align__(16) float g_y2[(size_t)ROWS*D2];
__device__ float g_gpool[BATCH*CIMG];
__device__ __align__(16) float g_dvec[BATCH*CIMG];
__device__ __align__(16) float g_Mt[BATCH][CIMG*D2];
__device__ float g_sum1[D1], g_ss1[D1], g_sum2[D2], g_ss2[D2];
__device__ __align__(16) uint4 g_B1f[2048];
__device__ __align__(16) uint4 g_B2f[2048];
__device__ __align__(16) uint4 g_B3f[BATCH][1024];
__device__ unsigned long long g_arrive;   // monotonic grid-barrier counter (never reset)

// ---------------- helpers ----------------
__device__ __forceinline__ void mma16816(float d[4], const uint32_t a[4], const uint32_t b[2]) {
    asm volatile("mma.sync.aligned.m16n8k16.row.col.f32.bf16.bf16.f32 "
        "{%0,%1,%2,%3}, {%4,%5,%6,%7}, {%8,%9}, {%0,%1,%2,%3};"
        : "+f"(d[0]), "+f"(d[1]), "+f"(d[2]), "+f"(d[3])
        : "r"(a[0]), "r"(a[1]), "r"(a[2]), "r"(a[3]), "r"(b[0]), "r"(b[1]));
}
__device__ __forceinline__ void split2(float a, float b, uint32_t& hi, uint32_t& lo) {
    __nv_bfloat16 ha = __float2bfloat16_rn(a), hb = __float2bfloat16_rn(b);
    float ra = a - __bfloat162float(ha), rb = b - __bfloat162float(hb);
    __nv_bfloat16 la = __float2bfloat16_rn(ra), lb = __float2bfloat16_rn(rb);
    hi = (uint32_t)__bfloat16_as_ushort(ha) | ((uint32_t)__bfloat16_as_ushort(hb) << 16);
    lo = (uint32_t)__bfloat16_as_ushort(la) | ((uint32_t)__bfloat16_as_ushort(lb) << 16);
}
__device__ __forceinline__ void loadA(const float* base, int ld, uint32_t aH[4], uint32_t aL[4]) {
    float2 v0 = *(const float2*)(base);
    float2 v1 = *(const float2*)(base + 8*ld);
    float2 v2 = *(const float2*)(base + 8);
    float2 v3 = *(const float2*)(base + 8*ld + 8);
    split2(v0.x, v0.y, aH[0], aL[0]);
    split2(v1.x, v1.y, aH[1], aL[1]);
    split2(v2.x, v2.y, aH[2], aL[2]);
    split2(v3.x, v3.y, aH[3], aL[3]);
}

// grid barrier: monotonic counter, each instance consumes NB arrivals
__device__ __forceinline__ void grid_bar() {
    __syncthreads();
    if (threadIdx.x == 0) {
        __threadfence();
        unsigned long long my = atomicAdd(&g_arrive, 1ULL) + 1ULL;
        unsigned long long target = ((my + (NB - 1)) / NB) * NB;
        for (;;) {
            unsigned long long cur;
            asm volatile("ld.volatile.global.u64 %0, [%1];" : "=l"(cur) : "l"(&g_arrive));
            if (cur >= target) break;
            __nanosleep(64);
        }
        __threadfence();
    }
    __syncthreads();
}

// ================ ONE persistent kernel ================
__global__ __launch_bounds__(256, 2) void k_fused(
    const float* __restrict__ lidar, const float* __restrict__ img,
    const float* __restrict__ W1,  const float* __restrict__ b1,
    const float* __restrict__ g1,  const float* __restrict__ be1,
    const float* __restrict__ W2,  const float* __restrict__ b2,
    const float* __restrict__ g2,  const float* __restrict__ be2,
    const float* __restrict__ W3,  const float* __restrict__ b3,
    float* __restrict__ out)
{
    __shared__ __align__(16) float smf[4608];
    int t = threadIdx.x, lane = t & 31;
    int bid = blockIdx.x;

    // ---------------- P0: pool_M (blocks 0..63) + weight pack + zero stats (64..79) ----------------
    if (bid >= 64 && bid < 80) {
        int i = (bid - 64) * 256 + t;    // 0..4095
        if (i < D1) { g_sum1[i] = 0.f; g_ss1[i] = 0.f; }
        if (i < D2) { g_sum2[i] = 0.f; g_ss2[i] = 0.f; }
        if (i < 2048) {
            int ln = i & 31, nt = (i >> 5) & 7, ks = (i >> 8) & 3, wn = i >> 10;
            int n = wn*64 + nt*8 + (ln >> 2);
            int k = ks*16 + (ln & 3)*2;
            const float* w = W1 + n*128 + 64 + k;
            uint32_t h0, l0, h1, l1;
            split2(w[0], w[1], h0, l0);
            split2(w[8], w[9], h1, l1);
            g_B1f[i] = make_uint4(h0, h1, l0, l1);
        } else {
            int j = i - 2048;
            int ln = j & 31, nt = (j >> 5) & 7, ks = j >> 8;
            int n = nt*8 + (ln >> 2);
            int k = ks*16 + (ln & 3)*2;
            const float* w = W2 + n*128 + k;
            uint32_t h0, l0, h1, l1;
            split2(w[0], w[1], h0, l0);
            split2(w[8], w[9], h1, l1);
            g_B2f[j] = make_uint4(h0, h1, l0, l1);
        }
    } else if (bid < 64) {
        float* srow = smf;              // [4][1024]
        float* red  = smf + 4096;       // [256]
        float* red2 = smf + 4352;       // [256]
        int b  = bid >> 4;
        int cg = bid & 15;
        int ci = t >> 6, l64 = t & 63;
        int c  = cg*4 + ci;
        const float* row = img + (size_t)(b*CIMG + c)*KIMG;

        float s = 0.f, sd = 0.f;
        for (int k = l64; k < KIMG; k += 64) {
            float v = row[k];
            srow[ci*KIMG + k] = v;
            s += v; sd += v * b3[k];
        }
        red[t] = s; red2[t] = sd;
        __syncthreads();
        for (int off = 32; off >= 1; off >>= 1) {
            if (l64 < off) { red[t] += red[t+off]; red2[t] += red2[t+off]; }
            __syncthreads();
        }
        if (l64 == 0) {
            g_gpool[b*CIMG + c] = red[t]  * (1.f/KIMG);
            g_dvec [b*CIMG + c] = red2[t] * (1.f/KIMG);
        }
        // parallel Mt: k split 4-way, float4 W3 loads (round-10 win)
        {
            int ks2 = t >> 6, ci2 = (t >> 4) & 3, tj = t & 15;
            float m0 = 0.f, m1 = 0.f, m2 = 0.f, m3 = 0.f;
            const float* srw = &srow[ci2*KIMG + ks2*256];
            const float4* wrow = (const float4*)W3 + (size_t)(ks2*256)*(D2/4) + tj;
            #pragma unroll 8
            for (int k = 0; k < 256; ++k) {
                float sv = srw[k];
                float4 w = wrow[k*16];
                m0 += sv*w.x; m1 += sv*w.y; m2 += sv*w.z; m3 += sv*w.w;
            }
            __syncthreads();
            *(float4*)&smf[ks2*256 + ci2*64 + tj*4] = make_float4(m0, m1, m2, m3);
            __syncthreads();
            int ci3 = t >> 6, j = t & 63;
            float acc = smf[ci3*64 + j] + smf[256 + ci3*64 + j]
                      + smf[512 + ci3*64 + j] + smf[768 + ci3*64 + j];
            g_Mt[b][(cg*4 + ci3)*D2 + j] = acc * (1.f/KIMG);
        }
    }
    grid_bar();

    // ---------------- P1: packB3 (blocks 0..15 only, then join) + GEMM1 ----------------
    if (bid < 16) {
        int i = bid * 256 + t;
        int ln = i & 31, nt = (i >> 5) & 7, ks = (i >> 8) & 3, b = i >> 10;
        int n = nt*8 + (ln >> 2);
        int k = ks*16 + (ln & 3)*2;
        const float* m = &g_Mt[b][n*D2 + k];
        uint32_t h0, l0, h1, l1;
        split2(m[0], m[1], h0, l0);
        split2(m[8], m[9], h1, l1);
        g_B3f[b][(ks*8 + nt)*32 + ln] = make_uint4(h0, h1, l0, l1);
    }
    // GEMM1 y1 = lidar·B1^T + h, fused stats (round-10 body; sH hoisted)
    {
        float* sH  = smf;          // [4][128] = 512
        float* sPS = smf + 512;    // [512]
        float* sPQ = smf + 1024;   // [512]
        {   // prologue: every block computes all h from gpool (cheap, L2-hot)
            int o = t & 127, b0 = t >> 7;
            float a0 = b1[o], a1 = b1[o];
            const float* wr = W1 + o*128;
            #pragma unroll 8
            for (int c = 0; c < 64; ++c) {
                float w = wr[c];
                a0 += g_gpool[b0*CIMG + c]     * w;
                a1 += g_gpool[(b0+2)*CIMG + c] * w;
            }
            sH[b0*128 + o]     = a0;
            sH[(b0+2)*128 + o] = a1;
        }
        __syncthreads();
        int wid = t >> 5, wm = wid >> 1, wn = wid & 1;
        for (int tile = bid; tile < 512; tile += NB) {
            size_t r0 = (size_t)tile * 128;
            int bidx = tile >> 7;

            float acc[2][8][4] = {};
            const float* abase = lidar + (r0 + wm*32 + (lane >> 2))*64 + (lane & 3)*2;
            const uint4* bbase = g_B1f + wn*1024 + lane;
            #pragma unroll
            for (int ks = 0; ks < 4; ++ks) {
                uint32_t aH[2][4], aL[2][4];
                loadA(abase + ks*16,         64, aH[0], aL[0]);
                loadA(abase + ks*16 + 16*64, 64, aH[1], aL[1]);
                uint32_t bH[8][2], bL[8][2];
                #pragma unroll
                for (int nt = 0; nt < 8; ++nt) {
                    uint4 f = bbase[(ks*8 + nt)*32];
                    bH[nt][0] = f.x; bH[nt][1] = f.y;
                    bL[nt][0] = f.z; bL[nt][1] = f.w;
                }
                #pragma unroll
                for (int mt = 0; mt < 2; ++mt)
                    #pragma unroll
                    for (int nt = 0; nt < 8; ++nt) {
                        mma16816(acc[mt][nt], aH[mt], bH[nt]);
                        mma16816(acc[mt][nt], aH[mt], bL[nt]);
                        mma16816(acc[mt][nt], aL[mt], bH[nt]);
                    }
            }

            float s[8][2], q[8][2];
            #pragma unroll
            for (int nt = 0; nt < 8; ++nt) { s[nt][0]=s[nt][1]=q[nt][0]=q[nt][1]=0.f; }
            int colb = wn*64 + (lane & 3)*2;
            int rb = wm*32 + (lane >> 2);
            #pragma unroll
            for (int nt = 0; nt < 8; ++nt) {
                int col = colb + nt*8;
                float h0 = sH[bidx*128 + col], h1 = sH[bidx*128 + col + 1];
                #pragma unroll
                for (int mt = 0; mt < 2; ++mt) {
                    float v0 = acc[mt][nt][0] + h0, v1 = acc[mt][nt][1] + h1;
                    float v2 = acc[mt][nt][2] + h0, v3 = acc[mt][nt][3] + h1;
                    size_t row = r0 + rb + mt*16;
                    *(float2*)&g_y1[row*D1 + col]       = make_float2(v0, v1);
                    *(float2*)&g_y1[(row + 8)*D1 + col] = make_float2(v2, v3);
                    s[nt][0] += v0 + v2;  s[nt][1] += v1 + v3;
                    q[nt][0] += v0*v0 + v2*v2;  q[nt][1] += v1*v1 + v3*v3;
                }
            }
            #pragma unroll
            for (int m = 4; m <= 16; m <<= 1)
                #pragma unroll
                for (int nt = 0; nt < 8; ++nt) {
                    s[nt][0] += __shfl_xor_sync(0xffffffffu, s[nt][0], m);
                    s[nt][1] += __shfl_xor_sync(0xffffffffu, s[nt][1], m);
                    q[nt][0] += __shfl_xor_sync(0xffffffffu, q[nt][0], m);
                    q[nt][1] += __shfl_xor_sync(0xffffffffu, q[nt][1], m);
                }
            if (lane < 4) {
                #pragma unroll
                for (int nt = 0; nt < 8; ++nt) {
                    int ch = wn*64 + nt*8 + lane*2;
                    sPS[wm*128 + ch]     = s[nt][0];
                    sPS[wm*128 + ch + 1] = s[nt][1];
                    sPQ[wm*128 + ch]     = q[nt][0];
                    sPQ[wm*128 + ch + 1] = q[nt][1];
                }
            }
            __syncthreads();
            if (t < 128) {
                float ss = 0.f, qq = 0.f;
                #pragma unroll
                for (int w = 0; w < 4; ++w) { ss += sPS[w*128 + t]; qq += sPQ[w*128 + t]; }
                atomicAdd(&g_sum1[t], ss);
                atomicAdd(&g_ss1[t],  qq);
            }
            __syncthreads();
        }
    }
    grid_bar();

    // ---------------- P2: GEMM2 y2 = relu(bn1(y1))·B2^T + b2, fused stats ----------------
    {
        float* sSC = smf;          // [128]
        float* sSH = smf + 128;    // [128]
        float* sBB = smf + 256;    // [64]
        float* sPS = smf + 320;    // [512]
        float* sPQ = smf + 832;    // [512]
        if (t < 128) {
            const float inv = 1.f / (float)ROWS;
            float mu  = g_sum1[t] * inv;
            float var = fmaxf(g_ss1[t] * inv - mu*mu, 0.f);
            float scale = g1[t] * rsqrtf(var + BN_EPS);
            sSC[t] = scale;
            sSH[t] = be1[t] - mu*scale;
        }
        if (t < 64) sBB[t] = b2[t];
        __syncthreads();
        int wm = t >> 5;
        int cb = (lane & 3)*2;
        for (int tile = bid; tile < 512; tile += NB) {
            size_t r0 = (size_t)tile * 128;

            float acc[8][4] = {};
            const float* abase = g_y1 + (r0 + wm*16 + (lane >> 2))*128 + cb;
            const uint4* bbase = g_B2f + lane;
            #pragma unroll
            for (int ks = 0; ks < 8; ++ks) {
                int c = ks*16 + cb;
                float2 sc0 = *(float2*)&sSC[c],     sh0 = *(float2*)&sSH[c];
                float2 sc1 = *(float2*)&sSC[c + 8], sh1 = *(float2*)&sSH[c + 8];
                const float* ap = abase + ks*16;
                float2 v0 = *(const float2*)(ap);
                float2 v1 = *(const float2*)(ap + 8*128);
                float2 v2 = *(const float2*)(ap + 8);
                float2 v3 = *(const float2*)(ap + 8*128 + 8);
                v0.x = fmaxf(fmaf(v0.x, sc0.x, sh0.x), 0.f);
                v0.y = fmaxf(fmaf(v0.y, sc0.y, sh0.y), 0.f);
                v1.x = fmaxf(fmaf(v1.x, sc0.x, sh0.x), 0.f);
                v1.y = fmaxf(fmaf(v1.y, sc0.y, sh0.y), 0.f);
                v2.x = fmaxf(fmaf(v2.x, sc1.x, sh1.x), 0.f);
                v2.y = fmaxf(fmaf(v2.y, sc1.y, sh1.y), 0.f);
                v3.x = fmaxf(fmaf(v3.x, sc1.x, sh1.x), 0.f);
                v3.y = fmaxf(fmaf(v3.y, sc1.y, sh1.y), 0.f);
                uint32_t aH[4], aL[4];
                split2(v0.x, v0.y, aH[0], aL[0]);
                split2(v1.x, v1.y, aH[1], aL[1]);
                split2(v2.x, v2.y, aH[2], aL[2]);
                split2(v3.x, v3.y, aH[3], aL[3]);
                #pragma unroll
                for (int nt = 0; nt < 8; ++nt) {
                    uint4 f = bbase[(ks*8 + nt)*32];
                    uint32_t bH[2] = { f.x, f.y }, bL[2] = { f.z, f.w };
                    mma16816(acc[nt], aH, bH);
                    mma16816(acc[nt], aH, bL);
                    mma16816(acc[nt], aL, bH);
                }
            }

            float s[8][2], q[8][2];
            #pragma unroll
            for (int nt = 0; nt < 8; ++nt) { s[nt][0]=s[nt][1]=q[nt][0]=q[nt][1]=0.f; }
            int rb = wm*16 + (lane >> 2);
            #pragma unroll
            for (int nt = 0; nt < 8; ++nt) {
                int col = cb + nt*8;
                float h0 = sBB[col], h1 = sBB[col + 1];
                float v0 = acc[nt][0] + h0, v1 = acc[nt][1] + h1;
                float v2 = acc[nt][2] + h0, v3 = acc[nt][3] + h1;
                size_t row = r0 + rb;
                *(float2*)&g_y2[row*D2 + col]       = make_float2(v0, v1);
                *(float2*)&g_y2[(row + 8)*D2 + col] = make_float2(v2, v3);
                s[nt][0] += v0 + v2;  s[nt][1] += v1 + v3;
                q[nt][0] += v0*v0 + v2*v2;  q[nt][1] += v1*v1 + v3*v3;
            }
            #pragma unroll
            for (int m = 4; m <= 16; m <<= 1)
                #pragma unroll
                for (int nt = 0; nt < 8; ++nt) {
                    s[nt][0] += __shfl_xor_sync(0xffffffffu, s[nt][0], m);
                    s[nt][1] += __shfl_xor_sync(0xffffffffu, s[nt][1], m);
                    q[nt][0] += __shfl_xor_sync(0xffffffffu, q[nt][0], m);
                    q[nt][1] += __shfl_xor_sync(0xffffffffu, q[nt][1], m);
                }
            if (lane < 4) {
                #pragma unroll
                for (int nt = 0; nt < 8; ++nt) {
                    int ch = nt*8 + lane*2;
                    sPS[wm*64 + ch]     = s[nt][0];
                    sPS[wm*64 + ch + 1] = s[nt][1];
                    sPQ[wm*64 + ch]     = q[nt][0];
                    sPQ[wm*64 + ch + 1] = q[nt][1];
                }
            }
            __syncthreads();
            if (t < 64) {
                float ss = 0.f, qq = 0.f;
                #pragma unroll
                for (int w = 0; w < 8; ++w) { ss += sPS[w*64 + t]; qq += sPQ[w*64 + t]; }
                atomicAdd(&g_sum2[t], ss);
                atomicAdd(&g_ss2[t],  qq);
            }
            __syncthreads();
        }
    }
    grid_bar();

    // ---------------- P3: GEMM3 out = relu(bn2(y2))·B3[b]^T + d[b] ----------------
    {
        float* sSC = smf;          // [64]
        float* sSH = smf + 64;     // [64]
        float* sDV = smf + 128;    // [4][64]
        if (t < 64) {
            const float inv = 1.f / (float)ROWS;
            float mu  = g_sum2[t] * inv;
            float var = fmaxf(g_ss2[t] * inv - mu*mu, 0.f);
            float scale = g2[t] * rsqrtf(var + BN_EPS);
            sSC[t] = scale;
            sSH[t] = be2[t] - mu*scale;
        }
        sDV[t] = g_dvec[t];        // 256 = 4*64
        __syncthreads();
        int wm = t >> 5;
        int cb = (lane & 3)*2;
        for (int tile = bid; tile < 512; tile += NB) {
            size_t r0 = (size_t)tile * 128;
            int bidx = tile >> 7;

            float acc[8][4] = {};
            const float* abase = g_y2 + (r0 + wm*16 + (lane >> 2))*64 + cb;
            const uint4* bbase = g_B3f[bidx] + lane;
            #pragma unroll
            for (int ks = 0; ks < 4; ++ks) {
                int c = ks*16 + cb;
                float2 sc0 = *(float2*)&sSC[c],     sh0 = *(float2*)&sSH[c];
                float2 sc1 = *(float2*)&sSC[c + 8], sh1 = *(float2*)&sSH[c + 8];
                const float* ap = abase + ks*16;
                float2 v0 = *(const float2*)(ap);
                float2 v1 = *(const float2*)(ap + 8*64);
                float2 v2 = *(const float2*)(ap + 8);
                float2 v3 = *(const float2*)(ap + 8*64 + 8);
                v0.x = fmaxf(fmaf(v0.x, sc0.x, sh0.x), 0.f);
                v0.y = fmaxf(fmaf(v0.y, sc0.y, sh0.y), 0.f);
                v1.x = fmaxf(fmaf(v1.x, sc0.x, sh0.x), 0.f);
                v1.y = fmaxf(fmaf(v1.y, sc0.y, sh0.y), 0.f);
                v2.x = fmaxf(fmaf(v2.x, sc1.x, sh1.x), 0.f);
                v2.y = fmaxf(fmaf(v2.y, sc1.y, sh1.y), 0.f);
                v3.x = fmaxf(fmaf(v3.x, sc1.x, sh1.x), 0.f);
                v3.y = fmaxf(fmaf(v3.y, sc1.y, sh1.y), 0.f);
                uint32_t aH[4], aL[4];
                split2(v0.x, v0.y, aH[0], aL[0]);
                split2(v1.x, v1.y, aH[1], aL[1]);
                split2(v2.x, v2.y, aH[2], aL[2]);
                split2(v3.x, v3.y, aH[3], aL[3]);
                #pragma unroll
                for (int nt = 0; nt < 8; ++nt) {
                    uint4 f = bbase[(ks*8 + nt)*32];
                    uint32_t bH[2] = { f.x, f.y }, bL[2] = { f.z, f.w };
                    mma16816(acc[nt], aH, bH);
                    mma16816(acc[nt], aH, bL);
                    mma16816(acc[nt], aL, bH);
                }
            }

            int rb = wm*16 + (lane >> 2);
            #pragma unroll
            for (int nt = 0; nt < 8; ++nt) {
                int col = cb + nt*8;
                float d0 = sDV[bidx*64 + col], d1 = sDV[bidx*64 + col + 1];
                size_t row = r0 + rb;
                *(float2*)&out[row*64 + col]       = make_float2(acc[nt][0] + d0, acc[nt][1] + d1);
                *(float2*)&out[(row + 8)*64 + col] = make_float2(acc[nt][2] + d0, acc[nt][3] + d1);
            }
        }
    }
}

// ---------------- launch ----------------
extern "C" void kernel_launch(void* const* d_in, const int* in_sizes, int n_in,
                              void* d_out, int out_size) {
    (void)in_sizes; (void)n_in; (void)out_size;
    const float* lidar = (const float*)d_in[0];
    const float* img   = (const float*)d_in[1];
    const float* W1  = (const float*)d_in[2];
    const float* b1  = (const float*)d_in[3];
    const float* g1  = (const float*)d_in[4];
    const float* be1 = (const float*)d_in[5];
    const float* W2  = (const float*)d_in[6];
    const float* b2  = (const float*)d_in[7];
    const float* g2  = (const float*)d_in[8];
    const float* be2 = (const float*)d_in[9];
    const float* W3  = (const float*)d_in[10];
    const float* b3  = (const float*)d_in[11];
    float* out = (float*)d_out;

    k_fused<<<NB, 256>>>(lidar, img, W1, b1, g1, be1, W2, b2, g2, be2, W3, b3, out);
}

// round 16
// speedup vs baseline: 1.2154x; 1.2154x over previous
#include <cuda_runtime.h>
#include <cuda_bf16.h>
#include <cstdint>

#define BATCH 4
#define NPTS  16384
#define ROWS  (BATCH*NPTS)     // 65536
#define CIMG  64
#define KIMG  1024
#define D1    128
#define D2    64
#define BN_EPS 1e-5f
#define NB    296              // persistent blocks (2 per SM on 148 SMs)

// ---------------- global scratch (no allocations allowed) ----------------
__device__ __align__(16) float g_y1[(size_t)ROWS*D1];
__device__ __align__(16) float g_y2[(size_t)ROWS*D2];
__device__ float g_gpool[BATCH*CIMG];
__device__ __align__(16) float g_h[BATCH*D1];
__device__ __align__(16) float g_dvec[BATCH*CIMG];
__device__ __align__(16) float g_Mt[BATCH][CIMG*D2];
__device__ float g_sum1[D1], g_ss1[D1], g_sum2[D2], g_ss2[D2];
__device__ __align__(16) uint4 g_B1f[2048];
__device__ __align__(16) uint4 g_B2f[2048];
__device__ __align__(16) uint4 g_B3f[BATCH][1024];
__device__ unsigned long long g_arrive;   // monotonic grid-barrier counter (never reset)

// ---------------- helpers ----------------
__device__ __forceinline__ void mma16816(float d[4], const uint32_t a[4], const uint32_t b[2]) {
    asm volatile("mma.sync.aligned.m16n8k16.row.col.f32.bf16.bf16.f32 "
        "{%0,%1,%2,%3}, {%4,%5,%6,%7}, {%8,%9}, {%0,%1,%2,%3};"
        : "+f"(d[0]), "+f"(d[1]), "+f"(d[2]), "+f"(d[3])
        : "r"(a[0]), "r"(a[1]), "r"(a[2]), "r"(a[3]), "r"(b[0]), "r"(b[1]));
}
__device__ __forceinline__ void split2(float a, float b, uint32_t& hi, uint32_t& lo) {
    __nv_bfloat16 ha = __float2bfloat16_rn(a), hb = __float2bfloat16_rn(b);
    float ra = a - __bfloat162float(ha), rb = b - __bfloat162float(hb);
    __nv_bfloat16 la = __float2bfloat16_rn(ra), lb = __float2bfloat16_rn(rb);
    hi = (uint32_t)__bfloat16_as_ushort(ha) | ((uint32_t)__bfloat16_as_ushort(hb) << 16);
    lo = (uint32_t)__bfloat16_as_ushort(la) | ((uint32_t)__bfloat16_as_ushort(lb) << 16);
}
__device__ __forceinline__ void loadA(const float* base, int ld, uint32_t aH[4], uint32_t aL[4]) {
    float2 v0 = *(const float2*)(base);
    float2 v1 = *(const float2*)(base + 8*ld);
    float2 v2 = *(const float2*)(base + 8);
    float2 v3 = *(const float2*)(base + 8*ld + 8);
    split2(v0.x, v0.y, aH[0], aL[0]);
    split2(v1.x, v1.y, aH[1], aL[1]);
    split2(v2.x, v2.y, aH[2], aL[2]);
    split2(v3.x, v3.y, aH[3], aL[3]);
}

// grid barrier: monotonic counter, each instance consumes NB arrivals
__device__ __forceinline__ void grid_bar() {
    __syncthreads();
    if (threadIdx.x == 0) {
        __threadfence();
        unsigned long long my = atomicAdd(&g_arrive, 1ULL) + 1ULL;
        unsigned long long target = ((my + (NB - 1)) / NB) * NB;
        for (;;) {
            unsigned long long cur;
            asm volatile("ld.volatile.global.u64 %0, [%1];" : "=l"(cur) : "l"(&g_arrive));
            if (cur >= target) break;
            __nanosleep(64);
        }
        __threadfence();
    }
    __syncthreads();
}

// ================ ONE persistent kernel ================
__global__ __launch_bounds__(256, 2) void k_fused(
    const float* __restrict__ lidar, const float* __restrict__ img,
    const float* __restrict__ W1,  const float* __restrict__ b1,
    const float* __restrict__ g1,  const float* __restrict__ be1,
    const float* __restrict__ W2,  const float* __restrict__ b2,
    const float* __restrict__ g2,  const float* __restrict__ be2,
    const float* __restrict__ W3,  const float* __restrict__ b3,
    float* __restrict__ out)
{
    __shared__ __align__(16) float smf[4608];
    int t = threadIdx.x, lane = t & 31;
    int bid = blockIdx.x;

    // ---------------- P0: pool_M (blocks 0..63) + weight pack + zero stats (64..79) ----------------
    if (bid >= 64 && bid < 80) {
        int i = (bid - 64) * 256 + t;    // 0..4095
        if (i < D1) { g_sum1[i] = 0.f; g_ss1[i] = 0.f; }
        if (i < D2) { g_sum2[i] = 0.f; g_ss2[i] = 0.f; }
        if (i < 2048) {
            int ln = i & 31, nt = (i >> 5) & 7, ks = (i >> 8) & 3, wn = i >> 10;
            int n = wn*64 + nt*8 + (ln >> 2);
            int k = ks*16 + (ln & 3)*2;
            const float* w = W1 + n*128 + 64 + k;
            uint32_t h0, l0, h1, l1;
            split2(w[0], w[1], h0, l0);
            split2(w[8], w[9], h1, l1);
            g_B1f[i] = make_uint4(h0, h1, l0, l1);
        } else {
            int j = i - 2048;
            int ln = j & 31, nt = (j >> 5) & 7, ks = j >> 8;
            int n = nt*8 + (ln >> 2);
            int k = ks*16 + (ln & 3)*2;
            const float* w = W2 + n*128 + k;
            uint32_t h0, l0, h1, l1;
            split2(w[0], w[1], h0, l0);
            split2(w[8], w[9], h1, l1);
            g_B2f[j] = make_uint4(h0, h1, l0, l1);
        }
    } else if (bid < 64) {
        float* srow = smf;              // [4][1024]
        float* red  = smf + 4096;       // [256]
        float* red2 = smf + 4352;       // [256]
        int b  = bid >> 4;
        int cg = bid & 15;
        int ci = t >> 6, l64 = t & 63;
        int c  = cg*4 + ci;
        const float* row = img + (size_t)(b*CIMG + c)*KIMG;

        float s = 0.f, sd = 0.f;
        for (int k = l64; k < KIMG; k += 64) {
            float v = row[k];
            srow[ci*KIMG + k] = v;
            s += v; sd += v * b3[k];
        }
        red[t] = s; red2[t] = sd;
        __syncthreads();
        for (int off = 32; off >= 1; off >>= 1) {
            if (l64 < off) { red[t] += red[t+off]; red2[t] += red2[t+off]; }
            __syncthreads();
        }
        if (l64 == 0) {
            g_gpool[b*CIMG + c] = red[t]  * (1.f/KIMG);
            g_dvec [b*CIMG + c] = red2[t] * (1.f/KIMG);
        }
        // parallel Mt: k split 4-way, float4 W3 loads (round-10 win)
        {
            int ks2 = t >> 6, ci2 = (t >> 4) & 3, tj = t & 15;
            float m0 = 0.f, m1 = 0.f, m2 = 0.f, m3 = 0.f;
            const float* srw = &srow[ci2*KIMG + ks2*256];
            const float4* wrow = (const float4*)W3 + (size_t)(ks2*256)*(D2/4) + tj;
            #pragma unroll 8
            for (int k = 0; k < 256; ++k) {
                float sv = srw[k];
                float4 w = wrow[k*16];
                m0 += sv*w.x; m1 += sv*w.y; m2 += sv*w.z; m3 += sv*w.w;
            }
            __syncthreads();
            *(float4*)&smf[ks2*256 + ci2*64 + tj*4] = make_float4(m0, m1, m2, m3);
            __syncthreads();
            int ci3 = t >> 6, j = t & 63;
            float acc = smf[ci3*64 + j] + smf[256 + ci3*64 + j]
                      + smf[512 + ci3*64 + j] + smf[768 + ci3*64 + j];
            g_Mt[b][(cg*4 + ci3)*D2 + j] = acc * (1.f/KIMG);
        }
    }
    grid_bar();

    // ---------------- P0.5: packB3 (blocks 0..15) + h (blocks 16..23) ----------------
    if (bid < 16) {
        int i = bid * 256 + t;
        int ln = i & 31, nt = (i >> 5) & 7, ks = (i >> 8) & 3, b = i >> 10;
        int n = nt*8 + (ln >> 2);
        int k = ks*16 + (ln & 3)*2;
        const float* m = &g_Mt[b][n*D2 + k];
        uint32_t h0, l0, h1, l1;
        split2(m[0], m[1], h0, l0);
        split2(m[8], m[9], h1, l1);
        g_B3f[b][(ks*8 + nt)*32 + ln] = make_uint4(h0, h1, l0, l1);
    } else if (bid < 24) {
        int idx = (bid - 16) * 64 + (t >> 2);   // 0..511
        int part = t & 3;
        int b = idx >> 7, o = idx & 127;
        float acc = 0.f;
        #pragma unroll
        for (int c = part*16; c < part*16 + 16; ++c)
            acc += g_gpool[b*CIMG + c] * W1[o*128 + c];
        acc += __shfl_xor_sync(0xffffffffu, acc, 1);
        acc += __shfl_xor_sync(0xffffffffu, acc, 2);
        if (part == 0) g_h[b*D1 + o] = acc + b1[o];
    }
    grid_bar();

    // ---------------- P1: GEMM1 y1 = lidar·B1^T + h, fused stats ----------------
    {
        float* sH  = smf;          // [4][128] = 512  (hoisted once)
        float* sPS = smf + 512;    // [512]
        float* sPQ = smf + 1024;   // [512]
        if (t < 128) {
            sH[t]       = g_h[t];
            sH[128 + t] = g_h[128 + t];
            sH[256 + t] = g_h[256 + t];
            sH[384 + t] = g_h[384 + t];
        }
        __syncthreads();
        int wid = t >> 5, wm = wid >> 1, wn = wid & 1;
        for (int tile = bid; tile < 512; tile += NB) {
            size_t r0 = (size_t)tile * 128;
            int bidx = tile >> 7;

            float acc[2][8][4] = {};
            const float* abase = lidar + (r0 + wm*32 + (lane >> 2))*64 + (lane & 3)*2;
            const uint4* bbase = g_B1f + wn*1024 + lane;
            #pragma unroll
            for (int ks = 0; ks < 4; ++ks) {
                uint32_t aH[2][4], aL[2][4];
                loadA(abase + ks*16,         64, aH[0], aL[0]);
                loadA(abase + ks*16 + 16*64, 64, aH[1], aL[1]);
                uint32_t bH[8][2], bL[8][2];
                #pragma unroll
                for (int nt = 0; nt < 8; ++nt) {
                    uint4 f = bbase[(ks*8 + nt)*32];
                    bH[nt][0] = f.x; bH[nt][1] = f.y;
                    bL[nt][0] = f.z; bL[nt][1] = f.w;
                }
                #pragma unroll
                for (int mt = 0; mt < 2; ++mt)
                    #pragma unroll
                    for (int nt = 0; nt < 8; ++nt) {
                        mma16816(acc[mt][nt], aH[mt], bH[nt]);
                        mma16816(acc[mt][nt], aH[mt], bL[nt]);
                        mma16816(acc[mt][nt], aL[mt], bH[nt]);
                    }
            }

            float s[8][2], q[8][2];
            #pragma unroll
            for (int nt = 0; nt < 8; ++nt) { s[nt][0]=s[nt][1]=q[nt][0]=q[nt][1]=0.f; }
            int colb = wn*64 + (lane & 3)*2;
            int rb = wm*32 + (lane >> 2);
            #pragma unroll
            for (int nt = 0; nt < 8; ++nt) {
                int col = colb + nt*8;
                float h0 = sH[bidx*128 + col], h1 = sH[bidx*128 + col + 1];
                #pragma unroll
                for (int mt = 0; mt < 2; ++mt) {
                    float v0 = acc[mt][nt][0] + h0, v1 = acc[mt][nt][1] + h1;
                    float v2 = acc[mt][nt][2] + h0, v3 = acc[mt][nt][3] + h1;
                    size_t row = r0 + rb + mt*16;
                    *(float2*)&g_y1[row*D1 + col]       = make_float2(v0, v1);
                    *(float2*)&g_y1[(row + 8)*D1 + col] = make_float2(v2, v3);
                    s[nt][0] += v0 + v2;  s[nt][1] += v1 + v3;
                    q[nt][0] += v0*v0 + v2*v2;  q[nt][1] += v1*v1 + v3*v3;
                }
            }
            #pragma unroll
            for (int m = 4; m <= 16; m <<= 1)
                #pragma unroll
                for (int nt = 0; nt < 8; ++nt) {
                    s[nt][0] += __shfl_xor_sync(0xffffffffu, s[nt][0], m);
                    s[nt][1] += __shfl_xor_sync(0xffffffffu, s[nt][1], m);
                    q[nt][0] += __shfl_xor_sync(0xffffffffu, q[nt][0], m);
                    q[nt][1] += __shfl_xor_sync(0xffffffffu, q[nt][1], m);
                }
            if (lane < 4) {
                #pragma unroll
                for (int nt = 0; nt < 8; ++nt) {
                    int ch = wn*64 + nt*8 + lane*2;
                    sPS[wm*128 + ch]     = s[nt][0];
                    sPS[wm*128 + ch + 1] = s[nt][1];
                    sPQ[wm*128 + ch]     = q[nt][0];
                    sPQ[wm*128 + ch + 1] = q[nt][1];
                }
            }
            __syncthreads();
            if (t < 128) {
                float ss = 0.f, qq = 0.f;
                #pragma unroll
                for (int w = 0; w < 4; ++w) { ss += sPS[w*128 + t]; qq += sPQ[w*128 + t]; }
                atomicAdd(&g_sum1[t], ss);
                atomicAdd(&g_ss1[t],  qq);
            }
            __syncthreads();
        }
    }
    grid_bar();

    // ---------------- P2: GEMM2 y2 = relu(bn1(y1))·B2^T + b2, fused stats ----------------
    {
        float* sSC = smf;          // [128]
        float* sSH = smf + 128;    // [128]
        float* sBB = smf + 256;    // [64]
        float* sPS = smf + 320;    // [512]
        float* sPQ = smf + 832;    // [512]
        if (t < 128) {
            const float inv = 1.f / (float)ROWS;
            float mu  = g_sum1[t] * inv;
            float var = fmaxf(g_ss1[t] * inv - mu*mu, 0.f);
            float scale = g1[t] * rsqrtf(var + BN_EPS);
            sSC[t] = scale;
            sSH[t] = be1[t] - mu*scale;
        }
        if (t < 64) sBB[t] = b2[t];
        __syncthreads();
        int wm = t >> 5;
        int cb = (lane & 3)*2;
        for (int tile = bid; tile < 512; tile += NB) {
            size_t r0 = (size_t)tile * 128;

            float acc[8][4] = {};
            const float* abase = g_y1 + (r0 + wm*16 + (lane >> 2))*128 + cb;
            const uint4* bbase = g_B2f + lane;
            #pragma unroll
            for (int ks = 0; ks < 8; ++ks) {
                int c = ks*16 + cb;
                float2 sc0 = *(float2*)&sSC[c],     sh0 = *(float2*)&sSH[c];
                float2 sc1 = *(float2*)&sSC[c + 8], sh1 = *(float2*)&sSH[c + 8];
                const float* ap = abase + ks*16;
                float2 v0 = *(const float2*)(ap);
                float2 v1 = *(const float2*)(ap + 8*128);
                float2 v2 = *(const float2*)(ap + 8);
                float2 v3 = *(const float2*)(ap + 8*128 + 8);
                v0.x = fmaxf(fmaf(v0.x, sc0.x, sh0.x), 0.f);
                v0.y = fmaxf(fmaf(v0.y, sc0.y, sh0.y), 0.f);
                v1.x = fmaxf(fmaf(v1.x, sc0.x, sh0.x), 0.f);
                v1.y = fmaxf(fmaf(v1.y, sc0.y, sh0.y), 0.f);
                v2.x = fmaxf(fmaf(v2.x, sc1.x, sh1.x), 0.f);
                v2.y = fmaxf(fmaf(v2.y, sc1.y, sh1.y), 0.f);
                v3.x = fmaxf(fmaf(v3.x, sc1.x, sh1.x), 0.f);
                v3.y = fmaxf(fmaf(v3.y, sc1.y, sh1.y), 0.f);
                uint32_t aH[4], aL[4];
                split2(v0.x, v0.y, aH[0], aL[0]);
                split2(v1.x, v1.y, aH[1], aL[1]);
                split2(v2.x, v2.y, aH[2], aL[2]);
                split2(v3.x, v3.y, aH[3], aL[3]);
                #pragma unroll
                for (int nt = 0; nt < 8; ++nt) {
                    uint4 f = bbase[(ks*8 + nt)*32];
                    uint32_t bH[2] = { f.x, f.y }, bL[2] = { f.z, f.w };
                    mma16816(acc[nt], aH, bH);
                    mma16816(acc[nt], aH, bL);
                    mma16816(acc[nt], aL, bH);
                }
            }

            float s[8][2], q[8][2];
            #pragma unroll
            for (int nt = 0; nt < 8; ++nt) { s[nt][0]=s[nt][1]=q[nt][0]=q[nt][1]=0.f; }
            int rb = wm*16 + (lane >> 2);
            #pragma unroll
            for (int nt = 0; nt < 8; ++nt) {
                int col = cb + nt*8;
                float h0 = sBB[col], h1 = sBB[col + 1];
                float v0 = acc[nt][0] + h0, v1 = acc[nt][1] + h1;
                float v2 = acc[nt][2] + h0, v3 = acc[nt][3] + h1;
                size_t row = r0 + rb;
                *(float2*)&g_y2[row*D2 + col]       = make_float2(v0, v1);
                *(float2*)&g_y2[(row + 8)*D2 + col] = make_float2(v2, v3);
                s[nt][0] += v0 + v2;  s[nt][1] += v1 + v3;
                q[nt][0] += v0*v0 + v2*v2;  q[nt][1] += v1*v1 + v3*v3;
            }
            #pragma unroll
            for (int m = 4; m <= 16; m <<= 1)
                #pragma unroll
                for (int nt = 0; nt < 8; ++nt) {
                    s[nt][0] += __shfl_xor_sync(0xffffffffu, s[nt][0], m);
                    s[nt][1] += __shfl_xor_sync(0xffffffffu, s[nt][1], m);
                    q[nt][0] += __shfl_xor_sync(0xffffffffu, q[nt][0], m);
                    q[nt][1] += __shfl_xor_sync(0xffffffffu, q[nt][1], m);
                }
            if (lane < 4) {
                #pragma unroll
                for (int nt = 0; nt < 8; ++nt) {
                    int ch = nt*8 + lane*2;
                    sPS[wm*64 + ch]     = s[nt][0];
                    sPS[wm*64 + ch + 1] = s[nt][1];
                    sPQ[wm*64 + ch]     = q[nt][0];
                    sPQ[wm*64 + ch + 1] = q[nt][1];
                }
            }
            __syncthreads();
            if (t < 64) {
                float ss = 0.f, qq = 0.f;
                #pragma unroll
                for (int w = 0; w < 8; ++w) { ss += sPS[w*64 + t]; qq += sPQ[w*64 + t]; }
                atomicAdd(&g_sum2[t], ss);
                atomicAdd(&g_ss2[t],  qq);
            }
            __syncthreads();
        }
    }
    grid_bar();

    // ---------------- P3: GEMM3 out = relu(bn2(y2))·B3[b]^T + d[b] ----------------
    {
        float* sSC = smf;          // [64]
        float* sSH = smf + 64;     // [64]
        float* sDV = smf + 128;    // [4][64]
        if (t < 64) {
            const float inv = 1.f / (float)ROWS;
            float mu  = g_sum2[t] * inv;
            float var = fmaxf(g_ss2[t] * inv - mu*mu, 0.f);
            float scale = g2[t] * rsqrtf(var + BN_EPS);
            sSC[t] = scale;
            sSH[t] = be2[t] - mu*scale;
        }
        sDV[t] = g_dvec[t];        // 256 = 4*64
        __syncthreads();
        int wm = t >> 5;
        int cb = (lane & 3)*2;
        for (int tile = bid; tile < 512; tile += NB) {
            size_t r0 = (size_t)tile * 128;
            int bidx = tile >> 7;

            float acc[8][4] = {};
            const float* abase = g_y2 + (r0 + wm*16 + (lane >> 2))*64 + cb;
            const uint4* bbase = g_B3f[bidx] + lane;
            #pragma unroll
            for (int ks = 0; ks < 4; ++ks) {
                int c = ks*16 + cb;
                float2 sc0 = *(float2*)&sSC[c],     sh0 = *(float2*)&sSH[c];
                float2 sc1 = *(float2*)&sSC[c + 8], sh1 = *(float2*)&sSH[c + 8];
                const float* ap = abase + ks*16;
                float2 v0 = *(const float2*)(ap);
                float2 v1 = *(const float2*)(ap + 8*64);
                float2 v2 = *(const float2*)(ap + 8);
                float2 v3 = *(const float2*)(ap + 8*64 + 8);
                v0.x = fmaxf(fmaf(v0.x, sc0.x, sh0.x), 0.f);
                v0.y = fmaxf(fmaf(v0.y, sc0.y, sh0.y), 0.f);
                v1.x = fmaxf(fmaf(v1.x, sc0.x, sh0.x), 0.f);
                v1.y = fmaxf(fmaf(v1.y, sc0.y, sh0.y), 0.f);
                v2.x = fmaxf(fmaf(v2.x, sc1.x, sh1.x), 0.f);
                v2.y = fmaxf(fmaf(v2.y, sc1.y, sh1.y), 0.f);
                v3.x = fmaxf(fmaf(v3.x, sc1.x, sh1.x), 0.f);
                v3.y = fmaxf(fmaf(v3.y, sc1.y, sh1.y), 0.f);
                uint32_t aH[4], aL[4];
                split2(v0.x, v0.y, aH[0], aL[0]);
                split2(v1.x, v1.y, aH[1], aL[1]);
                split2(v2.x, v2.y, aH[2], aL[2]);
                split2(v3.x, v3.y, aH[3], aL[3]);
                #pragma unroll
                for (int nt = 0; nt < 8; ++nt) {
                    uint4 f = bbase[(ks*8 + nt)*32];
                    uint32_t bH[2] = { f.x, f.y }, bL[2] = { f.z, f.w };
                    mma16816(acc[nt], aH, bH);
                    mma16816(acc[nt], aH, bL);
                    mma16816(acc[nt], aL, bH);
                }
            }

            int rb = wm*16 + (lane >> 2);
            #pragma unroll
            for (int nt = 0; nt < 8; ++nt) {
                int col = cb + nt*8;
                float d0 = sDV[bidx*64 + col], d1 = sDV[bidx*64 + col + 1];
                size_t row = r0 + rb;
                *(float2*)&out[row*64 + col]       = make_float2(acc[nt][0] + d0, acc[nt][1] + d1);
                *(float2*)&out[(row + 8)*64 + col] = make_float2(acc[nt][2] + d0, acc[nt][3] + d1);
            }
        }
    }
}

// ---------------- launch ----------------
extern "C" void kernel_launch(void* const* d_in, const int* in_sizes, int n_in,
                              void* d_out, int out_size) {
    (void)in_sizes; (void)n_in; (void)out_size;
    const float* lidar = (const float*)d_in[0];
    const float* img   = (const float*)d_in[1];
    const float* W1  = (const float*)d_in[2];
    const float* b1  = (const float*)d_in[3];
    const float* g1  = (const float*)d_in[4];
    const float* be1 = (const float*)d_in[5];
    const float* W2  = (const float*)d_in[6];
    const float* b2  = (const float*)d_in[7];
    const float* g2  = (const float*)d_in[8];
    const float* be2 = (const float*)d_in[9];
    const float* W3  = (const float*)d_in[10];
    const float* b3  = (const float*)d_in[11];
    float* out = (float*)d_out;

    k_fused<<<NB, 256>>>(lidar, img, W1, b1, g1, be1, W2, b2, g2, be2, W3, b3, out);
}

// round 17
// speedup vs baseline: 1.2642x; 1.0401x over previous
#include <cuda_runtime.h>
#include <cuda_bf16.h>
#include <cstdint>

#define BATCH 4
#define NPTS  16384
#define ROWS  (BATCH*NPTS)     // 65536
#define CIMG  64
#define KIMG  1024
#define D1    128
#define D2    64
#define BN_EPS 1e-5f
#define NB    296              // persistent blocks (2 per SM on 148 SMs)

// ---------------- global scratch (no allocations allowed) ----------------
__device__ __align__(16) float g_y1[(size_t)ROWS*D1];
__device__ __align__(16) float g_y2[(size_t)ROWS*D2];
__device__ float g_gpool[BATCH*CIMG];
__device__ __align__(16) float g_h[BATCH*D1];
__device__ __align__(16) float g_dvec[BATCH*CIMG];
__device__ __align__(16) float g_Mt[BATCH][CIMG*D2];
__device__ float g_sum1[D1], g_ss1[D1], g_sum2[D2], g_ss2[D2];
__device__ __align__(16) uint4 g_B1f[2048];
__device__ __align__(16) uint4 g_B2f[2048];
__device__ __align__(16) uint4 g_B3f[BATCH][1024];
__device__ unsigned long long g_arrive;   // monotonic grid-barrier counter (never reset)

// ---------------- helpers ----------------
__device__ __forceinline__ void mma16816(float d[4], const uint32_t a[4], const uint32_t b[2]) {
    asm volatile("mma.sync.aligned.m16n8k16.row.col.f32.bf16.bf16.f32 "
        "{%0,%1,%2,%3}, {%4,%5,%6,%7}, {%8,%9}, {%0,%1,%2,%3};"
        : "+f"(d[0]), "+f"(d[1]), "+f"(d[2]), "+f"(d[3])
        : "r"(a[0]), "r"(a[1]), "r"(a[2]), "r"(a[3]), "r"(b[0]), "r"(b[1]));
}
__device__ __forceinline__ void split2(float a, float b, uint32_t& hi, uint32_t& lo) {
    __nv_bfloat16 ha = __float2bfloat16_rn(a), hb = __float2bfloat16_rn(b);
    float ra = a - __bfloat162float(ha), rb = b - __bfloat162float(hb);
    __nv_bfloat16 la = __float2bfloat16_rn(ra), lb = __float2bfloat16_rn(rb);
    hi = (uint32_t)__bfloat16_as_ushort(ha) | ((uint32_t)__bfloat16_as_ushort(hb) << 16);
    lo = (uint32_t)__bfloat16_as_ushort(la) | ((uint32_t)__bfloat16_as_ushort(lb) << 16);
}
__device__ __forceinline__ void loadA(const float* base, int ld, uint32_t aH[4], uint32_t aL[4]) {
    float2 v0 = *(const float2*)(base);
    float2 v1 = *(const float2*)(base + 8*ld);
    float2 v2 = *(const float2*)(base + 8);
    float2 v3 = *(const float2*)(base + 8*ld + 8);
    split2(v0.x, v0.y, aH[0], aL[0]);
    split2(v1.x, v1.y, aH[1], aL[1]);
    split2(v2.x, v2.y, aH[2], aL[2]);
    split2(v3.x, v3.y, aH[3], aL[3]);
}

// grid barrier: monotonic counter, each instance consumes NB arrivals
__device__ __forceinline__ void grid_bar() {
    __syncthreads();
    if (threadIdx.x == 0) {
        __threadfence();
        unsigned long long my = atomicAdd(&g_arrive, 1ULL) + 1ULL;
        unsigned long long target = ((my + (NB - 1)) / NB) * NB;
        for (;;) {
            unsigned long long cur;
            asm volatile("ld.volatile.global.u64 %0, [%1];" : "=l"(cur) : "l"(&g_arrive));
            if (cur >= target) break;
            __nanosleep(64);
        }
        __threadfence();
    }
    __syncthreads();
}

// ================ ONE persistent kernel ================
__global__ __launch_bounds__(256, 2) void k_fused(
    const float* __restrict__ lidar, const float* __restrict__ img,
    const float* __restrict__ W1,  const float* __restrict__ b1,
    const float* __restrict__ g1,  const float* __restrict__ be1,
    const float* __restrict__ W2,  const float* __restrict__ b2,
    const float* __restrict__ g2,  const float* __restrict__ be2,
    const float* __restrict__ W3,  const float* __restrict__ b3,
    float* __restrict__ out)
{
    __shared__ __align__(16) float smf[4608];
    int t = threadIdx.x, lane = t & 31;
    int bid = blockIdx.x;

    // ---------------- P0: pool_M (blocks 0..63) + weight pack + zero stats (64..79) ----------------
    if (bid >= 64 && bid < 80) {
        int i = (bid - 64) * 256 + t;    // 0..4095
        if (i < D1) { g_sum1[i] = 0.f; g_ss1[i] = 0.f; }
        if (i < D2) { g_sum2[i] = 0.f; g_ss2[i] = 0.f; }
        if (i < 2048) {
            int ln = i & 31, nt = (i >> 5) & 7, ks = (i >> 8) & 3, wn = i >> 10;
            int n = wn*64 + nt*8 + (ln >> 2);
            int k = ks*16 + (ln & 3)*2;
            const float* w = W1 + n*128 + 64 + k;
            uint32_t h0, l0, h1, l1;
            split2(w[0], w[1], h0, l0);
            split2(w[8], w[9], h1, l1);
            g_B1f[i] = make_uint4(h0, h1, l0, l1);
        } else {
            int j = i - 2048;
            int ln = j & 31, nt = (j >> 5) & 7, ks = j >> 8;
            int n = nt*8 + (ln >> 2);
            int k = ks*16 + (ln & 3)*2;
            const float* w = W2 + n*128 + k;
            uint32_t h0, l0, h1, l1;
            split2(w[0], w[1], h0, l0);
            split2(w[8], w[9], h1, l1);
            g_B2f[j] = make_uint4(h0, h1, l0, l1);
        }
    } else if (bid < 64) {
        float* srow = smf;              // [4][1024]
        float* red  = smf + 4096;       // [256]
        float* red2 = smf + 4352;       // [256]
        int b  = bid >> 4;
        int cg = bid & 15;
        int ci = t >> 6, l64 = t & 63;
        int c  = cg*4 + ci;
        const float* row = img + (size_t)(b*CIMG + c)*KIMG;

        float s = 0.f, sd = 0.f;
        for (int k = l64; k < KIMG; k += 64) {
            float v = row[k];
            srow[ci*KIMG + k] = v;
            s += v; sd += v * b3[k];
        }
        red[t] = s; red2[t] = sd;
        __syncthreads();
        for (int off = 32; off >= 1; off >>= 1) {
            if (l64 < off) { red[t] += red[t+off]; red2[t] += red2[t+off]; }
            __syncthreads();
        }
        if (l64 == 0) {
            g_gpool[b*CIMG + c] = red[t]  * (1.f/KIMG);
            g_dvec [b*CIMG + c] = red2[t] * (1.f/KIMG);
        }
        // parallel Mt: k split 4-way, float4 W3 loads (round-10 win)
        {
            int ks2 = t >> 6, ci2 = (t >> 4) & 3, tj = t & 15;
            float m0 = 0.f, m1 = 0.f, m2 = 0.f, m3 = 0.f;
            const float* srw = &srow[ci2*KIMG + ks2*256];
            const float4* wrow = (const float4*)W3 + (size_t)(ks2*256)*(D2/4) + tj;
            #pragma unroll 8
            for (int k = 0; k < 256; ++k) {
                float sv = srw[k];
                float4 w = wrow[k*16];
                m0 += sv*w.x; m1 += sv*w.y; m2 += sv*w.z; m3 += sv*w.w;
            }
            __syncthreads();
            *(float4*)&smf[ks2*256 + ci2*64 + tj*4] = make_float4(m0, m1, m2, m3);
            __syncthreads();
            int ci3 = t >> 6, j = t & 63;
            float acc = smf[ci3*64 + j] + smf[256 + ci3*64 + j]
                      + smf[512 + ci3*64 + j] + smf[768 + ci3*64 + j];
            g_Mt[b][(cg*4 + ci3)*D2 + j] = acc * (1.f/KIMG);
        }
    }
    grid_bar();

    // ---------------- P0.5: packB3 (blocks 0..15) + h (blocks 16..23) ----------------
    if (bid < 16) {
        int i = bid * 256 + t;
        int ln = i & 31, nt = (i >> 5) & 7, ks = (i >> 8) & 3, b = i >> 10;
        int n = nt*8 + (ln >> 2);
        int k = ks*16 + (ln & 3)*2;
        const float* m = &g_Mt[b][n*D2 + k];
        uint32_t h0, l0, h1, l1;
        split2(m[0], m[1], h0, l0);
        split2(m[8], m[9], h1, l1);
        g_B3f[b][(ks*8 + nt)*32 + ln] = make_uint4(h0, h1, l0, l1);
    } else if (bid < 24) {
        int idx = (bid - 16) * 64 + (t >> 2);   // 0..511
        int part = t & 3;
        int b = idx >> 7, o = idx & 127;
        float acc = 0.f;
        #pragma unroll
        for (int c = part*16; c < part*16 + 16; ++c)
            acc += g_gpool[b*CIMG + c] * W1[o*128 + c];
        acc += __shfl_xor_sync(0xffffffffu, acc, 1);
        acc += __shfl_xor_sync(0xffffffffu, acc, 2);
        if (part == 0) g_h[b*D1 + o] = acc + b1[o];
    }
    grid_bar();

    // ---------------- P1: GEMM1 y1 = lidar·B1^T + h, fused stats (double-buffered partials) ----------------
    {
        float* sH  = smf;          // [4][128] = 512
        float* sPS = smf + 512;    // [2][512]
        float* sPQ = smf + 1536;   // [2][512]
        if (t < 128) {
            sH[t]       = g_h[t];
            sH[128 + t] = g_h[128 + t];
            sH[256 + t] = g_h[256 + t];
            sH[384 + t] = g_h[384 + t];
        }
        __syncthreads();
        int wid = t >> 5, wm = wid >> 1, wn = wid & 1;
        int it = 0;
        for (int tile = bid; tile < 512; tile += NB, ++it) {
            size_t r0 = (size_t)tile * 128;
            int bidx = tile >> 7;
            int pb = (it & 1) * 512;

            float acc[2][8][4] = {};
            const float* abase = lidar + (r0 + wm*32 + (lane >> 2))*64 + (lane & 3)*2;
            const uint4* bbase = g_B1f + wn*1024 + lane;
            #pragma unroll
            for (int ks = 0; ks < 4; ++ks) {
                uint32_t aH[2][4], aL[2][4];
                loadA(abase + ks*16,         64, aH[0], aL[0]);
                loadA(abase + ks*16 + 16*64, 64, aH[1], aL[1]);
                uint32_t bH[8][2], bL[8][2];
                #pragma unroll
                for (int nt = 0; nt < 8; ++nt) {
                    uint4 f = bbase[(ks*8 + nt)*32];
                    bH[nt][0] = f.x; bH[nt][1] = f.y;
                    bL[nt][0] = f.z; bL[nt][1] = f.w;
                }
                #pragma unroll
                for (int mt = 0; mt < 2; ++mt)
                    #pragma unroll
                    for (int nt = 0; nt < 8; ++nt) {
                        mma16816(acc[mt][nt], aH[mt], bH[nt]);
                        mma16816(acc[mt][nt], aH[mt], bL[nt]);
                        mma16816(acc[mt][nt], aL[mt], bH[nt]);
                    }
            }

            float s[8][2], q[8][2];
            #pragma unroll
            for (int nt = 0; nt < 8; ++nt) { s[nt][0]=s[nt][1]=q[nt][0]=q[nt][1]=0.f; }
            int colb = wn*64 + (lane & 3)*2;
            int rb = wm*32 + (lane >> 2);
            #pragma unroll
            for (int nt = 0; nt < 8; ++nt) {
                int col = colb + nt*8;
                float h0 = sH[bidx*128 + col], h1 = sH[bidx*128 + col + 1];
                #pragma unroll
                for (int mt = 0; mt < 2; ++mt) {
                    float v0 = acc[mt][nt][0] + h0, v1 = acc[mt][nt][1] + h1;
                    float v2 = acc[mt][nt][2] + h0, v3 = acc[mt][nt][3] + h1;
                    size_t row = r0 + rb + mt*16;
                    *(float2*)&g_y1[row*D1 + col]       = make_float2(v0, v1);
                    *(float2*)&g_y1[(row + 8)*D1 + col] = make_float2(v2, v3);
                    s[nt][0] += v0 + v2;  s[nt][1] += v1 + v3;
                    q[nt][0] += v0*v0 + v2*v2;  q[nt][1] += v1*v1 + v3*v3;
                }
            }
            #pragma unroll
            for (int m = 4; m <= 16; m <<= 1)
                #pragma unroll
                for (int nt = 0; nt < 8; ++nt) {
                    s[nt][0] += __shfl_xor_sync(0xffffffffu, s[nt][0], m);
                    s[nt][1] += __shfl_xor_sync(0xffffffffu, s[nt][1], m);
                    q[nt][0] += __shfl_xor_sync(0xffffffffu, q[nt][0], m);
                    q[nt][1] += __shfl_xor_sync(0xffffffffu, q[nt][1], m);
                }
            if (lane < 4) {
                #pragma unroll
                for (int nt = 0; nt < 8; ++nt) {
                    int ch = wn*64 + nt*8 + lane*2;
                    sPS[pb + wm*128 + ch]     = s[nt][0];
                    sPS[pb + wm*128 + ch + 1] = s[nt][1];
                    sPQ[pb + wm*128 + ch]     = q[nt][0];
                    sPQ[pb + wm*128 + ch + 1] = q[nt][1];
                }
            }
            __syncthreads();
            if (t < 128) {
                float ss = 0.f, qq = 0.f;
                #pragma unroll
                for (int w = 0; w < 4; ++w) { ss += sPS[pb + w*128 + t]; qq += sPQ[pb + w*128 + t]; }
                atomicAdd(&g_sum1[t], ss);
                atomicAdd(&g_ss1[t],  qq);
            }
        }
    }
    grid_bar();

    // ---------------- P2: GEMM2 y2 = relu(bn1(y1))·B2^T + b2, fused stats (double-buffered) ----------------
    {
        float* sSC = smf;          // [128]
        float* sSH = smf + 128;    // [128]
        float* sBB = smf + 256;    // [64]
        float* sPS = smf + 320;    // [2][512]
        float* sPQ = smf + 1344;   // [2][512]
        if (t < 128) {
            const float inv = 1.f / (float)ROWS;
            float mu  = g_sum1[t] * inv;
            float var = fmaxf(g_ss1[t] * inv - mu*mu, 0.f);
            float scale = g1[t] * rsqrtf(var + BN_EPS);
            sSC[t] = scale;
            sSH[t] = be1[t] - mu*scale;
        }
        if (t < 64) sBB[t] = b2[t];
        __syncthreads();
        int wm = t >> 5;
        int cb = (lane & 3)*2;
        int it = 0;
        for (int tile = bid; tile < 512; tile += NB, ++it) {
            size_t r0 = (size_t)tile * 128;
            int pb = (it & 1) * 512;

            float acc[8][4] = {};
            const float* abase = g_y1 + (r0 + wm*16 + (lane >> 2))*128 + cb;
            const uint4* bbase = g_B2f + lane;
            #pragma unroll
            for (int ks = 0; ks < 8; ++ks) {
                int c = ks*16 + cb;
                float2 sc0 = *(float2*)&sSC[c],     sh0 = *(float2*)&sSH[c];
                float2 sc1 = *(float2*)&sSC[c + 8], sh1 = *(float2*)&sSH[c + 8];
                const float* ap = abase + ks*16;
                float2 v0 = *(const float2*)(ap);
                float2 v1 = *(const float2*)(ap + 8*128);
                float2 v2 = *(const float2*)(ap + 8);
                float2 v3 = *(const float2*)(ap + 8*128 + 8);
                v0.x = fmaxf(fmaf(v0.x, sc0.x, sh0.x), 0.f);
                v0.y = fmaxf(fmaf(v0.y, sc0.y, sh0.y), 0.f);
                v1.x = fmaxf(fmaf(v1.x, sc0.x, sh0.x), 0.f);
                v1.y = fmaxf(fmaf(v1.y, sc0.y, sh0.y), 0.f);
                v2.x = fmaxf(fmaf(v2.x, sc1.x, sh1.x), 0.f);
                v2.y = fmaxf(fmaf(v2.y, sc1.y, sh1.y), 0.f);
                v3.x = fmaxf(fmaf(v3.x, sc1.x, sh1.x), 0.f);
                v3.y = fmaxf(fmaf(v3.y, sc1.y, sh1.y), 0.f);
                uint32_t aH[4], aL[4];
                split2(v0.x, v0.y, aH[0], aL[0]);
                split2(v1.x, v1.y, aH[1], aL[1]);
                split2(v2.x, v2.y, aH[2], aL[2]);
                split2(v3.x, v3.y, aH[3], aL[3]);
                #pragma unroll
                for (int nt = 0; nt < 8; ++nt) {
                    uint4 f = bbase[(ks*8 + nt)*32];
                    uint32_t bH[2] = { f.x, f.y }, bL[2] = { f.z, f.w };
                    mma16816(acc[nt], aH, bH);
                    mma16816(acc[nt], aH, bL);
                    mma16816(acc[nt], aL, bH);
                }
            }

            float s[8][2], q[8][2];
            #pragma unroll
            for (int nt = 0; nt < 8; ++nt) { s[nt][0]=s[nt][1]=q[nt][0]=q[nt][1]=0.f; }
            int rb = wm*16 + (lane >> 2);
            #pragma unroll
            for (int nt = 0; nt < 8; ++nt) {
                int col = cb + nt*8;
                float h0 = sBB[col], h1 = sBB[col + 1];
                float v0 = acc[nt][0] + h0, v1 = acc[nt][1] + h1;
                float v2 = acc[nt][2] + h0, v3 = acc[nt][3] + h1;
                size_t row = r0 + rb;
                *(float2*)&g_y2[row*D2 + col]       = make_float2(v0, v1);
                *(float2*)&g_y2[(row + 8)*D2 + col] = make_float2(v2, v3);
                s[nt][0] += v0 + v2;  s[nt][1] += v1 + v3;
                q[nt][0] += v0*v0 + v2*v2;  q[nt][1] += v1*v1 + v3*v3;
            }
            #pragma unroll
            for (int m = 4; m <= 16; m <<= 1)
                #pragma unroll
                for (int nt = 0; nt < 8; ++nt) {
                    s[nt][0] += __shfl_xor_sync(0xffffffffu, s[nt][0], m);
                    s[nt][1] += __shfl_xor_sync(0xffffffffu, s[nt][1], m);
                    q[nt][0] += __shfl_xor_sync(0xffffffffu, q[nt][0], m);
                    q[nt][1] += __shfl_xor_sync(0xffffffffu, q[nt][1], m);
                }
            if (lane < 4) {
                #pragma unroll
                for (int nt = 0; nt < 8; ++nt) {
                    int ch = nt*8 + lane*2;
                    sPS[pb + wm*64 + ch]     = s[nt][0];
                    sPS[pb + wm*64 + ch + 1] = s[nt][1];
                    sPQ[pb + wm*64 + ch]     = q[nt][0];
                    sPQ[pb + wm*64 + ch + 1] = q[nt][1];
                }
            }
            __syncthreads();
            if (t < 64) {
                float ss = 0.f, qq = 0.f;
                #pragma unroll
                for (int w = 0; w < 8; ++w) { ss += sPS[pb + w*64 + t]; qq += sPQ[pb + w*64 + t]; }
                atomicAdd(&g_sum2[t], ss);
                atomicAdd(&g_ss2[t],  qq);
            }
        }
    }
    grid_bar();

    // ---------------- P3: GEMM3 out = relu(bn2(y2))·B3[b]^T + d[b] ----------------
    {
        float* sSC = smf;          // [64]
        float* sSH = smf + 64;     // [64]
        float* sDV = smf + 128;    // [4][64]
        if (t < 64) {
            const float inv = 1.f / (float)ROWS;
            float mu  = g_sum2[t] * inv;
            float var = fmaxf(g_ss2[t] * inv - mu*mu, 0.f);
            float scale = g2[t] * rsqrtf(var + BN_EPS);
            sSC[t] = scale;
            sSH[t] = be2[t] - mu*scale;
        }
        sDV[t] = g_dvec[t];        // 256 = 4*64
        __syncthreads();
        int wm = t >> 5;
        int cb = (lane & 3)*2;
        for (int tile = bid; tile < 512; tile += NB) {
            size_t r0 = (size_t)tile * 128;
            int bidx = tile >> 7;

            float acc[8][4] = {};
            const float* abase = g_y2 + (r0 + wm*16 + (lane >> 2))*64 + cb;
            const uint4* bbase = g_B3f[bidx] + lane;
            #pragma unroll
            for (int ks = 0; ks < 4; ++ks) {
                int c = ks*16 + cb;
                float2 sc0 = *(float2*)&sSC[c],     sh0 = *(float2*)&sSH[c];
                float2 sc1 = *(float2*)&sSC[c + 8], sh1 = *(float2*)&sSH[c + 8];
                const float* ap = abase + ks*16;
                float2 v0 = *(const float2*)(ap);
                float2 v1 = *(const float2*)(ap + 8*64);
                float2 v2 = *(const float2*)(ap + 8);
                float2 v3 = *(const float2*)(ap + 8*64 + 8);
                v0.x = fmaxf(fmaf(v0.x, sc0.x, sh0.x), 0.f);
                v0.y = fmaxf(fmaf(v0.y, sc0.y, sh0.y), 0.f);
                v1.x = fmaxf(fmaf(v1.x, sc0.x, sh0.x), 0.f);
                v1.y = fmaxf(fmaf(v1.y, sc0.y, sh0.y), 0.f);
                v2.x = fmaxf(fmaf(v2.x, sc1.x, sh1.x), 0.f);
                v2.y = fmaxf(fmaf(v2.y, sc1.y, sh1.y), 0.f);
                v3.x = fmaxf(fmaf(v3.x, sc1.x, sh1.x), 0.f);
                v3.y = fmaxf(fmaf(v3.y, sc1.y, sh1.y), 0.f);
                uint32_t aH[4], aL[4];
                split2(v0.x, v0.y, aH[0], aL[0]);
                split2(v1.x, v1.y, aH[1], aL[1]);
                split2(v2.x, v2.y, aH[2], aL[2]);
                split2(v3.x, v3.y, aH[3], aL[3]);
                #pragma unroll
                for (int nt = 0; nt < 8; ++nt) {
                    uint4 f = bbase[(ks*8 + nt)*32];
                    uint32_t bH[2] = { f.x, f.y }, bL[2] = { f.z, f.w };
                    mma16816(acc[nt], aH, bH);
                    mma16816(acc[nt], aH, bL);
                    mma16816(acc[nt], aL, bH);
                }
            }

            int rb = wm*16 + (lane >> 2);
            #pragma unroll
            for (int nt = 0; nt < 8; ++nt) {
                int col = cb + nt*8;
                float d0 = sDV[bidx*64 + col], d1 = sDV[bidx*64 + col + 1];
                size_t row = r0 + rb;
                *(float2*)&out[row*64 + col]       = make_float2(acc[nt][0] + d0, acc[nt][1] + d1);
                *(float2*)&out[(row + 8)*64 + col] = make_float2(acc[nt][2] + d0, acc[nt][3] + d1);
            }
        }
    }
}

// ---------------- launch ----------------
extern "C" void kernel_launch(void* const* d_in, const int* in_sizes, int n_in,
                              void* d_out, int out_size) {
    (void)in_sizes; (void)n_in; (void)out_size;
    const float* lidar = (const float*)d_in[0];
    const float* img   = (const float*)d_in[1];
    const float* W1  = (const float*)d_in[2];
    const float* b1  = (const float*)d_in[3];
    const float* g1  = (const float*)d_in[4];
    const float* be1 = (const float*)d_in[5];
    const float* W2  = (const float*)d_in[6];
    const float* b2  = (const float*)d_in[7];
    const float* g2  = (const float*)d_in[8];
    const float* be2 = (const float*)d_in[9];
    const float* W3  = (const float*)d_in[10];
    const float* b3  = (const float*)d_in[11];
    float* out = (float*)d_out;

    k_fused<<<NB, 256>>>(lidar, img, W1, b1, g1, be1, W2, b2, g2, be2, W3, b3, out);
}